// round 9
// baseline (speedup 1.0000x reference)
#include <cuda_runtime.h>
#include <cstdint>

#define S_   24
#define B_   256
#define D_   1024
#define H_   16
#define DH_  64
#define L_   12
#define V_   32000
#define NTOK (S_ * B_)   // 6144

// Scratch (allocation-free rule: __device__ globals)
__device__ float    g_x [NTOK * D_];        // fp32 residual stream
__device__ uint32_t g_xr[NTOK * D_];        // tf32-rounded copy (GEMM A operand)
__device__ float    g_q [NTOK * D_];
__device__ float    g_k [NTOK * D_];
__device__ float    g_v [NTOK * D_];
__device__ uint32_t g_wq[(size_t)L_ * D_ * D_];   // tf32-rounded weights, all layers
__device__ uint32_t g_wk[(size_t)L_ * D_ * D_];
__device__ uint32_t g_wv[(size_t)L_ * D_ * D_];
__device__ uint32_t g_wo[(size_t)V_ * D_];

// ---------------------------------------------------------------------------
// Helpers
// ---------------------------------------------------------------------------
__device__ __forceinline__ uint32_t smem_u32(const void* p) {
    uint32_t a;
    asm("{ .reg .u64 t; cvta.to.shared.u64 t, %1; cvt.u32.u64 %0, t; }" : "=r"(a) : "l"(p));
    return a;
}
__device__ __forceinline__ uint32_t f2tf(float x) {
    uint32_t y;
    asm("cvt.rna.tf32.f32 %0, %1;" : "=r"(y) : "f"(x));
    return y;
}
template <int IMM>
__device__ __forceinline__ uint32_t ldso(uint32_t a) {
    uint32_t v;
    asm volatile("ld.shared.b32 %0, [%1+%2];" : "=r"(v) : "r"(a), "n"(IMM));
    return v;
}
__device__ __forceinline__ void mma_tf32(float* d, const uint32_t* a, const uint32_t* b) {
    asm volatile(
        "mma.sync.aligned.m16n8k8.row.col.f32.tf32.tf32.f32 "
        "{%0,%1,%2,%3}, {%4,%5,%6,%7}, {%8,%9}, {%0,%1,%2,%3};"
        : "+f"(d[0]), "+f"(d[1]), "+f"(d[2]), "+f"(d[3])
        : "r"(a[0]), "r"(a[1]), "r"(a[2]), "r"(a[3]), "r"(b[0]), "r"(b[1]));
}
#define CPA16(dst, src) asm volatile("cp.async.cg.shared.global [%0], [%1], 16;" \
    :: "r"(dst), "l"(src) : "memory")
#define CPA_COMMIT() asm volatile("cp.async.commit_group;" ::: "memory")
#define CPA_WAIT0()  asm volatile("cp.async.wait_group 0;" ::: "memory")

// ---------------------------------------------------------------------------
// Weight conversion: all layers, all three matrices, one launch.
// ---------------------------------------------------------------------------
__global__ void __launch_bounds__(256) conv_all_kernel(
    const float* __restrict__ qw, const float* __restrict__ kw,
    const float* __restrict__ vw)
{
    const size_t lo = (size_t)blockIdx.y * D_ * D_;
    const float* src;
    uint32_t* dst;
    if (blockIdx.z == 0)      { src = qw + lo; dst = g_wq + lo; }
    else if (blockIdx.z == 1) { src = kw + lo; dst = g_wk + lo; }
    else                      { src = vw + lo; dst = g_wv + lo; }
    size_t i = ((size_t)blockIdx.x * 256 + threadIdx.x) * 4;
    float4 v = *(const float4*)(src + i);
    uint4 o = { f2tf(v.x), f2tf(v.y), f2tf(v.z), f2tf(v.w) };
    *(uint4*)(dst + i) = o;
}

__global__ void __launch_bounds__(256) conv_out_kernel(const float* __restrict__ w)
{
    size_t i = ((size_t)blockIdx.x * 256 + threadIdx.x) * 4;
    float4 v = *(const float4*)(w + i);
    uint4 o = { f2tf(v.x), f2tf(v.y), f2tf(v.z), f2tf(v.w) };
    *(uint4*)(g_wo + i) = o;
}

// ---------------------------------------------------------------------------
// Embedding
// ---------------------------------------------------------------------------
__global__ void __launch_bounds__(256) embed_kernel(
    const int* __restrict__ inp,
    const float* __restrict__ tok,
    const float* __restrict__ pe)
{
    int e4 = blockIdx.x * 256 + threadIdx.x;
    int e  = e4 * 4;
    int n  = e / D_;
    int d  = e % D_;
    int s  = n / B_;
    int t  = inp[n];
    float4 a = *(const float4*)(tok + (size_t)t * D_ + d);
    float4 p = *(const float4*)(pe + (size_t)s * D_ + d);
    a.x += p.x; a.y += p.y; a.z += p.z; a.w += p.w;
    *(float4*)(g_x + e) = a;
    uint4 r = { f2tf(a.x), f2tf(a.y), f2tf(a.z), f2tf(a.w) };
    *(uint4*)(g_xr + e) = r;
}

// ---------------------------------------------------------------------------
// TF32 mma GEMM. BK=32 tiles, 3-stage cp.async ring, 4-slice inner pipeline,
// cross-tile A prefetch. Block tile 128x128, 8 warps @ 64x32, 2 CTAs/SM.
// Stage: A 16KB (128 rows x 128B) + B 16KB. Swizzle: chunk' = chunk ^ (row&7)
//   -> all fragment scalar LDS conflict-free (32 distinct banks / warp).
// ---------------------------------------------------------------------------
#define BK_    32
#define KT     (D_ / BK_)   // 32
#define STAGEB 32768u
#define SMEM_BYTES (3 * 32768)

template <bool STREAM>
__device__ __forceinline__ void gemm_body(
    const uint32_t* __restrict__ A, const uint32_t* __restrict__ Bw,
    const float* __restrict__ bias, float* __restrict__ C,
    int N, int bm, int bn)
{
    extern __shared__ char smem[];
    const uint32_t sbase = smem_u32(smem);

    const int tid  = threadIdx.x;
    const int lane = tid & 31;
    const int wid  = tid >> 5;
    const int grp  = lane >> 2;      // 0..7
    const int tig  = lane & 3;       // 0..3
    const int wm   = wid >> 2;       // 0..1
    const int wn   = wid & 3;        // 0..3

    // ---- producer mapping: row pm = tid>>1, chunk quad pu = (tid&1)*4 ----
    const int pm = tid >> 1;
    const int pu = (tid & 1) * 4;
    const uint32_t pkey = (uint32_t)(pm & 7);
    uint32_t po[4];
    #pragma unroll
    for (int c = 0; c < 4; c++)
        po[c] = (uint32_t)pm * 128u + ((((uint32_t)(pu + c)) ^ pkey) << 4);
    const uint32_t* agp = A  + (size_t)(bm + pm) * D_ + pu * 4;
    const uint32_t* bgp = Bw + (size_t)(bn + pm) * D_ + pu * 4;

    #define ISSUE_TO(stb, t) do {                                              \
        const uint32_t* a0 = agp + (t) * BK_;                                  \
        CPA16((stb) + po[0], a0);                                              \
        CPA16((stb) + po[1], a0 + 4);                                          \
        CPA16((stb) + po[2], a0 + 8);                                          \
        CPA16((stb) + po[3], a0 + 12);                                         \
        const uint32_t* b0 = bgp + (t) * BK_;                                  \
        CPA16((stb) + 16384u + po[0], b0);                                     \
        CPA16((stb) + 16384u + po[1], b0 + 4);                                 \
        CPA16((stb) + 16384u + po[2], b0 + 8);                                 \
        CPA16((stb) + 16384u + po[3], b0 + 12);                                \
    } while (0)

    float acc[4][4][4];
    #pragma unroll
    for (int i = 0; i < 4; i++)
        #pragma unroll
        for (int j = 0; j < 4; j++)
            #pragma unroll
            for (int c = 0; c < 4; c++) acc[i][j][c] = 0.f;

    // consumer folded bases: chunk XOR-key (= grp) lives in free bits 4..6
    const int m00 = wm * 64 + grp;
    const uint32_t a2 = (uint32_t)m00 * 128u + (uint32_t)tig * 4u + ((uint32_t)grp << 4);
    const int n00 = wn * 32 + grp;
    const uint32_t b2 = (uint32_t)n00 * 128u + (uint32_t)tig * 4u + ((uint32_t)grp << 4);

    // A frags, slice s: chunks 2s (k tig) and 2s+1 (k tig+4); rows m00+i*16, +8
    #define AF_LOAD(buf, ab, s) do {                                           \
        const uint32_t ra0 = (ab) + (a2 ^ (uint32_t)((2*(s))     << 4));       \
        const uint32_t ra1 = (ab) + (a2 ^ (uint32_t)((2*(s) + 1) << 4));       \
        buf[0][0] = ldso<0>(ra0);    buf[0][1] = ldso<1024>(ra0);              \
        buf[0][2] = ldso<0>(ra1);    buf[0][3] = ldso<1024>(ra1);              \
        buf[1][0] = ldso<2048>(ra0); buf[1][1] = ldso<3072>(ra0);              \
        buf[1][2] = ldso<2048>(ra1); buf[1][3] = ldso<3072>(ra1);              \
        buf[2][0] = ldso<4096>(ra0); buf[2][1] = ldso<5120>(ra0);              \
        buf[2][2] = ldso<4096>(ra1); buf[2][3] = ldso<5120>(ra1);              \
        buf[3][0] = ldso<6144>(ra0); buf[3][1] = ldso<7168>(ra0);              \
        buf[3][2] = ldso<6144>(ra1); buf[3][3] = ldso<7168>(ra1);              \
    } while (0)

    #define BF_LOAD(buf, bb, s) do {                                           \
        const uint32_t rb0 = (bb) + (b2 ^ (uint32_t)((2*(s))     << 4));       \
        const uint32_t rb1 = (bb) + (b2 ^ (uint32_t)((2*(s) + 1) << 4));       \
        buf[0][0] = ldso<0>(rb0);    buf[0][1] = ldso<0>(rb1);                 \
        buf[1][0] = ldso<1024>(rb0); buf[1][1] = ldso<1024>(rb1);              \
        buf[2][0] = ldso<2048>(rb0); buf[2][1] = ldso<2048>(rb1);              \
        buf[3][0] = ldso<3072>(rb0); buf[3][1] = ldso<3072>(rb1);              \
    } while (0)

    #define MMA_SLICE(af, bf)                                                  \
        _Pragma("unroll") for (int i = 0; i < 4; i++)                          \
            _Pragma("unroll") for (int j = 0; j < 4; j++)                      \
                mma_tf32(acc[i][j], af[i], bf[j]);

    // prologue: stages 0,1 filled and visible
    ISSUE_TO(sbase, 0);          CPA_COMMIT();
    ISSUE_TO(sbase + STAGEB, 1); CPA_COMMIT();
    CPA_WAIT0();
    __syncthreads();

    uint32_t afA[4][4], afB[4][4], bf[4][2];
    AF_LOAD(afA, sbase, 0);

    int stc = 0, stn = 1, sti = 2;
    for (int t = 0; t < KT; t++) {
        const uint32_t ab   = sbase + (uint32_t)stc * STAGEB;
        const uint32_t bb   = ab + 16384u;
        const uint32_t ab_n = sbase + (uint32_t)stn * STAGEB;

        // refill stage (t+2)%3 — its slot was consumed in iter t-1,
        // protected by last iter's barrier.
        if (t + 2 < KT) {
            const uint32_t ib = sbase + (uint32_t)sti * STAGEB;
            ISSUE_TO(ib, t + 2);
        }
        CPA_COMMIT();

        // 4 pipelined slices; 16 mmas each; A frags one slice ahead.
        BF_LOAD(bf, bb, 0); AF_LOAD(afB, ab, 1);   MMA_SLICE(afA, bf);
        BF_LOAD(bf, bb, 1); AF_LOAD(afA, ab, 2);   MMA_SLICE(afB, bf);
        BF_LOAD(bf, bb, 2); AF_LOAD(afB, ab, 3);   MMA_SLICE(afA, bf);
        BF_LOAD(bf, bb, 3); AF_LOAD(afA, ab_n, 0); MMA_SLICE(afB, bf);
        // (final iter's ab_n read is stale-but-valid smem; result unused)

        CPA_WAIT0();          // all issued stages complete (incl. t+1, t+2)
        __syncthreads();      // ... and visible; stage t free for reuse

        int tmp = stc; stc = stn; stn = sti; sti = tmp;
    }

    // ---- epilogue ----
    #pragma unroll
    for (int i = 0; i < 4; i++) {
        const int r0 = bm + wm * 64 + i * 16 + grp;
        #pragma unroll
        for (int j = 0; j < 4; j++) {
            const int col = bn + wn * 32 + j * 8 + tig * 2;
            float2 bv = *(const float2*)(bias + col);
            float2 v0 = { acc[i][j][0] + bv.x, acc[i][j][1] + bv.y };
            float2 v1 = { acc[i][j][2] + bv.x, acc[i][j][3] + bv.y };
            if (STREAM) {
                __stcs((float2*)(C + (size_t)r0 * N + col), v0);
                __stcs((float2*)(C + (size_t)(r0 + 8) * N + col), v1);
            } else {
                *(float2*)(C + (size_t)r0 * N + col)       = v0;
                *(float2*)(C + (size_t)(r0 + 8) * N + col) = v1;
            }
        }
    }
    #undef ISSUE_TO
    #undef AF_LOAD
    #undef BF_LOAD
    #undef MMA_SLICE
}

__global__ void __launch_bounds__(256, 2) qkv_gemm_kernel(
    const float* __restrict__ qb, const float* __restrict__ kb,
    const float* __restrict__ vb, int layer)
{
    const size_t lo = (size_t)layer * D_ * D_;
    const uint32_t* W; const float* bb; float* C;
    if (blockIdx.z == 0)      { W = g_wq + lo; bb = qb; C = g_q; }
    else if (blockIdx.z == 1) { W = g_wk + lo; bb = kb; C = g_k; }
    else                      { W = g_wv + lo; bb = vb; C = g_v; }
    gemm_body<false>(g_xr, W, bb, C, D_, blockIdx.x * 128, blockIdx.y * 128);
}

__global__ void __launch_bounds__(256, 2) out_gemm_kernel(
    const float* __restrict__ bias, float* __restrict__ C)
{
    gemm_body<true>(g_xr, g_wo, bias, C, V_, blockIdx.x * 128, blockIdx.y * 128);
}

// ---------------------------------------------------------------------------
// Attention: one block per (b, h). S=24, DH=64. Fused residual.
// ---------------------------------------------------------------------------
__global__ void __launch_bounds__(256) attn_kernel()
{
    __shared__ float qs[S_][DH_];
    __shared__ float ks_[S_][DH_];
    __shared__ float vs[S_][DH_];
    __shared__ float sc[S_][S_];

    const int bh  = blockIdx.x;
    const int b   = bh >> 4;
    const int h   = bh & 15;
    const int tid = threadIdx.x;

    for (int idx = tid; idx < S_ * DH_ / 4; idx += 256) {
        int s = idx >> 4, c4 = (idx & 15) * 4;
        size_t off = ((size_t)s * B_ + b) * D_ + h * DH_ + c4;
        *(float4*)&qs[s][c4]  = *(const float4*)(g_q + off);
        *(float4*)&ks_[s][c4] = *(const float4*)(g_k + off);
        *(float4*)&vs[s][c4]  = *(const float4*)(g_v + off);
    }
    __syncthreads();

    const float scale = 0.03125f;   // 1/sqrt(1024)
    for (int idx = tid; idx < S_ * S_; idx += 256) {
        int s = idx / S_, t = idx % S_;
        float dot = 0.f;
        #pragma unroll
        for (int d = 0; d < DH_; d++) dot = fmaf(qs[s][d], ks_[t][d], dot);
        sc[s][t] = dot * scale;
    }
    __syncthreads();

    if (tid < S_) {
        float m = -1e30f;
        #pragma unroll
        for (int t = 0; t < S_; t++) m = fmaxf(m, sc[tid][t]);
        float sum = 0.f;
        #pragma unroll
        for (int t = 0; t < S_; t++) {
            float e = expf(sc[tid][t] - m);
            sc[tid][t] = e;
            sum += e;
        }
        float inv = 1.f / sum;
        #pragma unroll
        for (int t = 0; t < S_; t++) sc[tid][t] *= inv;
    }
    __syncthreads();

    for (int idx = tid; idx < S_ * DH_ / 4; idx += 256) {
        int s = idx >> 4, c4 = (idx & 15) * 4;
        float4 o = {0.f, 0.f, 0.f, 0.f};
        #pragma unroll
        for (int t = 0; t < S_; t++) {
            float p = sc[s][t];
            float4 vv = *(const float4*)&vs[t][c4];
            o.x = fmaf(p, vv.x, o.x);
            o.y = fmaf(p, vv.y, o.y);
            o.z = fmaf(p, vv.z, o.z);
            o.w = fmaf(p, vv.w, o.w);
        }
        size_t off = ((size_t)s * B_ + b) * D_ + h * DH_ + c4;
        float4 xv = *(const float4*)(g_x + off);
        xv.x += o.x; xv.y += o.y; xv.z += o.z; xv.w += o.w;
        *(float4*)(g_x + off) = xv;
        uint4 r = { f2tf(xv.x), f2tf(xv.y), f2tf(xv.z), f2tf(xv.w) };
        *(uint4*)(g_xr + off) = r;
    }
}

// ---------------------------------------------------------------------------
// Launch
// ---------------------------------------------------------------------------
extern "C" void kernel_launch(void* const* d_in, const int* in_sizes, int n_in,
                              void* d_out, int out_size)
{
    const int*   inp = (const int*)  d_in[0];
    const float* tok = (const float*)d_in[2];
    const float* pe  = (const float*)d_in[3];
    const float* qw  = (const float*)d_in[4];
    const float* qb  = (const float*)d_in[5];
    const float* kw  = (const float*)d_in[6];
    const float* kb  = (const float*)d_in[7];
    const float* vw  = (const float*)d_in[8];
    const float* vb  = (const float*)d_in[9];
    const float* ow  = (const float*)d_in[10];
    const float* ob  = (const float*)d_in[11];
    float* out = (float*)d_out;

    cudaFuncSetAttribute(qkv_gemm_kernel, cudaFuncAttributeMaxDynamicSharedMemorySize, SMEM_BYTES);
    cudaFuncSetAttribute(out_gemm_kernel, cudaFuncAttributeMaxDynamicSharedMemorySize, SMEM_BYTES);

    embed_kernel<<<NTOK * D_ / 4 / 256, 256>>>(inp, tok, pe);
    conv_all_kernel<<<dim3(D_ * D_ / 4 / 256, L_, 3), 256>>>(qw, kw, vw);
    conv_out_kernel<<<(size_t)V_ * D_ / 4 / 256, 256>>>(ow);

    for (int l = 0; l < L_; l++) {
        const size_t bo = (size_t)l * D_;
        qkv_gemm_kernel<<<dim3(NTOK / 128, D_ / 128, 3), 256, SMEM_BYTES>>>(
            qb + bo, kb + bo, vb + bo, l);
        attn_kernel<<<B_ * H_, 256>>>();
    }

    out_gemm_kernel<<<dim3(NTOK / 128, V_ / 128), 256, SMEM_BYTES>>>(ob, out);
}